// round 9
// baseline (speedup 1.0000x reference)
#include <cuda_runtime.h>
#include <cuda_fp16.h>

#define NN 100000
#define NE 1600000
#define NS 3
#define DIN 128
#define DOUT 64
#define ROW (NS*DOUT)    /* 192 halfs per node state row */
#define HROW 96          /* 96 half2 per node row */
#define DEPTH 10

// ---------------- device scratch (static: no allocation allowed) ----------------
__device__ __half2 g_hA  [NN*HROW];    // fp16 state (double buffered)
__device__ __half2 g_hB  [NN*HROW];
__device__ __half2 g_temb[NN*HROW];    // fp16 t*emb (teleport term)
__device__ float   g_wt  [DOUT*DOUT];  // W_tgt transposed: g_wt[o*64+p] = W_tgt[p*64+o]
__device__ int     g_cnt[NN];
__device__ int     g_rowptr[NN+1];
__device__ int     g_cursor[NN];
__device__ float   g_deginv[NN];
__device__ int     g_col[NE];
__device__ int     g_scan[NN];
__device__ int     g_bsum[128];
__device__ int     g_boff[128];
__device__ int     g_done;     // zero at load; reset by last scan block each call

// packed f32x2 helpers (Blackwell: one issue slot per packed add)
__device__ __forceinline__ unsigned long long f32x2_add(unsigned long long a,
                                                        unsigned long long b) {
    unsigned long long r;
    asm("add.rn.f32x2 %0, %1, %2;" : "=l"(r) : "l"(a), "l"(b));
    return r;
}
__device__ __forceinline__ unsigned long long pack2(float2 v) {
    unsigned long long r;
    asm("mov.b64 %0, {%1, %2};" : "=l"(r) : "f"(v.x), "f"(v.y));
    return r;
}
__device__ __forceinline__ float2 unpack2(unsigned long long a) {
    float2 v;
    asm("mov.b64 {%0, %1}, %2;" : "=f"(v.x), "=f"(v.y) : "l"(a));
    return v;
}

// ---------------- launch 0: histogram (g_cnt zeroed by previous k_fill) ----------
__global__ void k_hist(const int* __restrict__ tgt) {
    int e = blockIdx.x*blockDim.x + threadIdx.x;
    if (e < NE) atomicAdd(&g_cnt[tgt[e]], 1);
}

// ---------------- launch 1: fused scan (decoupled last-block finish) --------------
__global__ void k_scan() {
    __shared__ int sh[1024];
    __shared__ bool s_last;
    int t = threadIdx.x;
    int i = blockIdx.x*1024 + t;
    int v = (i < NN) ? g_cnt[i] : 0;
    sh[t] = v;
    __syncthreads();
    for (int off = 1; off < 1024; off <<= 1) {
        int add = (t >= off) ? sh[t-off] : 0;
        __syncthreads();
        sh[t] += add;
        __syncthreads();
    }
    if (i < NN) g_scan[i] = sh[t];
    if (t == 1023) g_bsum[blockIdx.x] = sh[1023];
    __threadfence();
    if (t == 0) {
        int done = atomicAdd(&g_done, 1);
        s_last = (done == (int)gridDim.x - 1);
    }
    __syncthreads();
    if (!s_last) return;
    __threadfence();
    if (t == 0) {
        int run = 0;
        for (int b = 0; b < (int)gridDim.x; b++) { g_boff[b] = run; run += g_bsum[b]; }
        g_done = 0;
        g_rowptr[NN] = NE;
    }
    __syncthreads();
    for (int k = t; k < NN; k += 1024) {
        int cnt  = g_cnt[k];
        int excl = g_scan[k] - cnt + g_boff[k >> 10];
        g_rowptr[k] = excl;
        g_cursor[k] = excl;
        g_deginv[k] = 1.0f / (float)max(cnt, 1);
    }
}

// ---------------- launch 2: CSR fill (+re-zero g_cnt) + W_tgt transpose ----------
__global__ void __launch_bounds__(256) k_fill(const int* __restrict__ src,
                                              const int* __restrict__ tgt,
                                              const float* __restrict__ W_tgt) {
    int bid = blockIdx.x;
    int tid = threadIdx.x;
    if (bid == 6250) {                // W_tgt transpose (tiny, once)
        for (int i = tid; i < DOUT*DOUT; i += 256) {
            int p = i >> 6, o = i & 63;
            g_wt[o*DOUT + p] = W_tgt[i];
        }
        return;
    }
    int e = bid*256 + tid;
    if (e < NE) {
        int p = atomicAdd(&g_cursor[tgt[e]], 1);
        g_col[p] = src[e];
    }
    if (e < NN) g_cnt[e] = 0;         // ready for next replay's k_hist
}

// ---------------- launch 3: emb GEMM (profiled window next round) ----------------
// block = 16 nodes x 1 scale; thread computes 4 outputs with float4 W loads.
__global__ void __launch_bounds__(256) k_emb(const float* __restrict__ data,
                                             const float* __restrict__ Ws,
                                             const float* __restrict__ bs) {
    __shared__ float sd[16][DIN+1];
    int bid = blockIdx.x;
    int tid = threadIdx.x;
    int s  = bid / 6250;              // scale
    int n0 = (bid % 6250) * 16;       // first node
    for (int i = tid; i < 16*DIN; i += 256) {
        int rrow = i >> 7, col = i & 127;
        sd[rrow][col] = data[(size_t)n0*DIN + i];
    }
    __syncthreads();
    int row = tid >> 4;               // node within block (0..15)
    int og  = tid & 15;               // output group: outs og*4 .. og*4+3
    const float4* W4 = (const float4*)(Ws + (size_t)s*DIN*DOUT);
    float acc0 = bs[s*DOUT + og*4 + 0];
    float acc1 = bs[s*DOUT + og*4 + 1];
    float acc2 = bs[s*DOUT + og*4 + 2];
    float acc3 = bs[s*DOUT + og*4 + 3];
    #pragma unroll 4
    for (int k = 0; k < DIN; k++) {
        float d = sd[row][k];
        float4 wv = W4[k*16 + og];
        acc0 += d*wv.x; acc1 += d*wv.y; acc2 += d*wv.z; acc3 += d*wv.w;
    }
    const float tv[NS] = {0.1f, 0.2f, 0.3f};
    float t = tv[s];
    size_t idx2 = ((size_t)(n0 + row)*ROW + s*DOUT + og*4) >> 1;  // half2 units
    g_hA[idx2]     = __floats2half2_rn(acc0, acc1);
    g_hA[idx2 + 1] = __floats2half2_rn(acc2, acc3);
    g_temb[idx2]     = __floats2half2_rn(t*acc0, t*acc1);
    g_temb[idx2 + 1] = __floats2half2_rn(t*acc2, t*acc3);
}

// ---------------- launches 4..13: one propagation step, all 3 scales fused --------
// fp16-only state; packed f32x2 accumulators (half the FADD issue slots).
__global__ void __launch_bounds__(256) k_prop(const __half2* __restrict__ xh,
                                              __half2* __restrict__ yh) {
    int w    = (blockIdx.x*blockDim.x + threadIdx.x) >> 5;
    int lane = threadIdx.x & 31;
    if (w >= NN) return;
    int beg = g_rowptr[w], end = g_rowptr[w+1];

    unsigned long long a0 = 0ull, a1 = 0ull, a2 = 0ull;   // packed f32x2 sums

    int j = beg;
    for (; j + 4 <= end; j += 4) {
        int c0 = __ldg(&g_col[j+0]);
        int c1 = __ldg(&g_col[j+1]);
        int c2 = __ldg(&g_col[j+2]);
        int c3 = __ldg(&g_col[j+3]);
        const __half2* r0 = xh + (size_t)c0*HROW;
        const __half2* r1 = xh + (size_t)c1*HROW;
        const __half2* r2 = xh + (size_t)c2*HROW;
        const __half2* r3 = xh + (size_t)c3*HROW;
        __half2 h00 = r0[lane],    h10 = r1[lane],    h20 = r2[lane],    h30 = r3[lane];
        __half2 h01 = r0[32+lane], h11 = r1[32+lane], h21 = r2[32+lane], h31 = r3[32+lane];
        __half2 h02 = r0[64+lane], h12 = r1[64+lane], h22 = r2[64+lane], h32 = r3[64+lane];
        a0 = f32x2_add(a0, pack2(__half22float2(h00)));
        a0 = f32x2_add(a0, pack2(__half22float2(h10)));
        a0 = f32x2_add(a0, pack2(__half22float2(h20)));
        a0 = f32x2_add(a0, pack2(__half22float2(h30)));
        a1 = f32x2_add(a1, pack2(__half22float2(h01)));
        a1 = f32x2_add(a1, pack2(__half22float2(h11)));
        a1 = f32x2_add(a1, pack2(__half22float2(h21)));
        a1 = f32x2_add(a1, pack2(__half22float2(h31)));
        a2 = f32x2_add(a2, pack2(__half22float2(h02)));
        a2 = f32x2_add(a2, pack2(__half22float2(h12)));
        a2 = f32x2_add(a2, pack2(__half22float2(h22)));
        a2 = f32x2_add(a2, pack2(__half22float2(h32)));
    }
    for (; j < end; j++) {
        int c = __ldg(&g_col[j]);
        const __half2* r = xh + (size_t)c*HROW;
        a0 = f32x2_add(a0, pack2(__half22float2(r[lane])));
        a1 = f32x2_add(a1, pack2(__half22float2(r[32+lane])));
        a2 = f32x2_add(a2, pack2(__half22float2(r[64+lane])));
    }

    const __half2* tm = g_temb + (size_t)w*HROW;
    __half2* hr = yh + (size_t)w*HROW;

    if (end > beg) {
        float2 s0 = unpack2(a0), s1 = unpack2(a1), s2 = unpack2(a2);
        const __half2* xo = xh + (size_t)w*HROW;
        float dinv = g_deginv[w];
        const float i0 = 0.9f, i1 = 0.8f, i2 = 0.7f;  // (1 - t)
        float2 e0 = __half22float2(tm[lane]);
        float2 e1 = __half22float2(tm[32 + lane]);
        float2 e2 = __half22float2(tm[64 + lane]);
        float2 o0 = __half22float2(xo[lane]);
        float2 o1 = __half22float2(xo[32 + lane]);
        float2 o2 = __half22float2(xo[64 + lane]);
        float2 r;
        r.x = i0*(o0.x - s0.x*dinv) + e0.x;
        r.y = i0*(o0.y - s0.y*dinv) + e0.y;  hr[lane]      = __float22half2_rn(r);
        r.x = i1*(o1.x - s1.x*dinv) + e1.x;
        r.y = i1*(o1.y - s1.y*dinv) + e1.y;  hr[32 + lane] = __float22half2_rn(r);
        r.x = i2*(o2.x - s2.x*dinv) + e2.x;
        r.y = i2*(o2.y - s2.y*dinv) + e2.y;  hr[64 + lane] = __float22half2_rn(r);
    } else {
        hr[lane]      = tm[lane];
        hr[32 + lane] = tm[32 + lane];
        hr[64 + lane] = tm[64 + lane];
    }
}

// ---------------- launch 14: fused attention epilogue, warp per node --------------
// W_tgt read directly from pre-transposed global (16KB, L1-resident, coalesced).
__global__ void __launch_bounds__(256) k_final(
        const __half2* __restrict__ xin, const float* __restrict__ data,
        const float* __restrict__ W_src, const float* __restrict__ b_src,
        const float* __restrict__ b_tgt, float* __restrict__ out) {
    __shared__ float sd[8][DIN];
    __shared__ float ssf[8][DOUT];
    int tid  = threadIdx.x;
    int wid  = tid >> 5;
    int lane = tid & 31;
    int n = blockIdx.x*8 + wid;       // grid = NN/8 exactly

    float4 dv = ((const float4*)(data + (size_t)n*DIN))[lane];
    ((float4*)sd[wid])[lane] = dv;
    __syncthreads();

    // s_att pair (o = 2*lane, 2*lane+1)
    const float2* ws2 = (const float2*)W_src;
    float2 bsv = ((const float2*)b_src)[lane];
    float a0 = bsv.x, a1 = bsv.y;
    #pragma unroll 8
    for (int k = 0; k < DIN; k++) {
        float d = sd[wid][k];
        float2 wv = ws2[k*32 + lane];
        a0 += d * wv.x;
        a1 += d * wv.y;
    }
    ssf[wid][2*lane]     = a0;
    ssf[wid][2*lane + 1] = a1;
    __syncwarp();

    // scales = relu(state), pair layout
    const __half2* xr = xin + (size_t)n*HROW;
    float sc[NS][2];
    #pragma unroll
    for (int s = 0; s < NS; s++) {
        float2 v = __half22float2(xr[s*32 + lane]);
        sc[s][0] = fmaxf(v.x, 0.f);
        sc[s][1] = fmaxf(v.y, 0.f);
    }

    // u[p] for p = 2*lane, 2*lane+1 via pre-transposed W_tgt in global (L1 hits)
    const float2* wt2 = (const float2*)g_wt;
    float u0 = 0.f, u1 = 0.f;
    #pragma unroll 8
    for (int o = 0; o < DOUT; o++) {
        float sa = ssf[wid][o];
        float2 wv = __ldg(&wt2[o*32 + lane]);
        u0 += wv.x * sa;
        u1 += wv.y * sa;
    }

    float2 btv = ((const float2*)b_tgt)[lane];
    float cp = btv.x*a0 + btv.y*a1;
    for (int m = 16; m; m >>= 1) cp += __shfl_xor_sync(0xffffffffu, cp, m);

    float lg[NS];
    #pragma unroll
    for (int s = 0; s < NS; s++) {
        float p = sc[s][0]*u0 + sc[s][1]*u1;
        for (int m = 16; m; m >>= 1) p += __shfl_xor_sync(0xffffffffu, p, m);
        lg[s] = p + cp;
    }

    float mx = fmaxf(lg[0], fmaxf(lg[1], lg[2]));
    float e0 = expf(lg[0]-mx), e1 = expf(lg[1]-mx), e2 = expf(lg[2]-mx);
    float inv = 1.f / (e0 + e1 + e2);
    float w0 = e0*inv, w1 = e1*inv, w2 = e2*inv;

    float2 ov;
    ov.x = w0*sc[0][0] + w1*sc[1][0] + w2*sc[2][0];
    ov.y = w0*sc[0][1] + w1*sc[1][1] + w2*sc[2][1];
    ((float2*)out)[(size_t)n*32 + lane] = ov;
}

// ---------------- launch ----------------
extern "C" void kernel_launch(void* const* d_in, const int* in_sizes, int n_in,
                              void* d_out, int out_size) {
    const float* data  = (const float*)d_in[0];
    const int*   src   = (const int*)  d_in[1];
    const int*   tgt   = (const int*)  d_in[2];
    const float* Ws    = (const float*)d_in[3];
    const float* bs    = (const float*)d_in[4];
    const float* W_src = (const float*)d_in[5];
    const float* b_src = (const float*)d_in[6];
    const float* W_tgt = (const float*)d_in[7];
    const float* b_tgt = (const float*)d_in[8];
    float* out = (float*)d_out;

    k_hist<<<(NE+255)/256, 256>>>(tgt);            // launch 0
    k_scan<<<(NN+1023)/1024, 1024>>>();            // launch 1
    k_fill<<<6251, 256>>>(src, tgt, W_tgt);        // launch 2
    k_emb <<<6250*NS, 256>>>(data, Ws, bs);        // launch 3  <- profiled next round

    __half2 *hA, *hB;
    cudaGetSymbolAddress((void**)&hA, g_hA);
    cudaGetSymbolAddress((void**)&hB, g_hB);

    const __half2* cur = hA;
    __half2*       nxt = hB;
    for (int d = 0; d < DEPTH; d++) {              // launches 4..13
        k_prop<<<NN/8, 256>>>(cur, nxt);
        const __half2* tmp = nxt;
        nxt = (__half2*)cur;
        cur = tmp;
    }

    k_final<<<NN/8, 256>>>(cur, data, W_src, b_src, b_tgt, out);   // launch 14
}

// round 10
// speedup vs baseline: 1.1060x; 1.1060x over previous
#include <cuda_runtime.h>
#include <cuda_fp16.h>

#define NN 100000
#define NE 1600000
#define NS 3
#define DIN 128
#define DOUT 64
#define ROW (NS*DOUT)    /* 192 halfs per node state row */
#define HROW 96          /* 96 half2 per node row */
#define DEPTH 10

// ---------------- device scratch (static: no allocation allowed) ----------------
__device__ __half2 g_hA  [NN*HROW];    // fp16 state (double buffered)
__device__ __half2 g_hB  [NN*HROW];
__device__ __half2 g_temb[NN*HROW];    // fp16 t*emb (teleport term)
__device__ float   g_wt  [DOUT*DOUT];  // W_tgt transposed
__device__ int     g_cnt[NN];
__device__ int     g_rowptr[NN+1];
__device__ int     g_cursor[NN];
__device__ float   g_deginv[NN];
__device__ int     g_col[NE];
__device__ int     g_scan[NN];
__device__ int     g_bsum[128];
__device__ int     g_boff[128];
__device__ int     g_done;

// f32x2 helpers for the emb GEMM (FFMA2 only reachable via PTX)
__device__ __forceinline__ unsigned long long fma2(unsigned long long a,
                                                   unsigned long long b,
                                                   unsigned long long c) {
    unsigned long long r;
    asm("fma.rn.f32x2 %0, %1, %2, %3;" : "=l"(r) : "l"(a), "l"(b), "l"(c));
    return r;
}
__device__ __forceinline__ unsigned long long bcast2(float x) {
    unsigned long long r;
    asm("mov.b64 %0, {%1, %1};" : "=l"(r) : "f"(x));
    return r;
}
__device__ __forceinline__ float2 unpk2(unsigned long long a) {
    float2 v;
    asm("mov.b64 {%0, %1}, %2;" : "=f"(v.x), "=f"(v.y) : "l"(a));
    return v;
}

// ---------------- launch 0: histogram ----------------
__global__ void k_hist(const int* __restrict__ tgt) {
    int e = blockIdx.x*blockDim.x + threadIdx.x;
    if (e < NE) atomicAdd(&g_cnt[tgt[e]], 1);
}

// ---------------- launch 1: fused scan (decoupled last-block finish) ----------
__global__ void k_scan() {
    __shared__ int sh[1024];
    __shared__ bool s_last;
    int t = threadIdx.x;
    int i = blockIdx.x*1024 + t;
    int v = (i < NN) ? g_cnt[i] : 0;
    sh[t] = v;
    __syncthreads();
    for (int off = 1; off < 1024; off <<= 1) {
        int add = (t >= off) ? sh[t-off] : 0;
        __syncthreads();
        sh[t] += add;
        __syncthreads();
    }
    if (i < NN) g_scan[i] = sh[t];
    if (t == 1023) g_bsum[blockIdx.x] = sh[1023];
    __threadfence();
    if (t == 0) {
        int done = atomicAdd(&g_done, 1);
        s_last = (done == (int)gridDim.x - 1);
    }
    __syncthreads();
    if (!s_last) return;
    __threadfence();
    if (t == 0) {
        int run = 0;
        for (int b = 0; b < (int)gridDim.x; b++) { g_boff[b] = run; run += g_bsum[b]; }
        g_done = 0;
        g_rowptr[NN] = NE;
    }
    __syncthreads();
    for (int k = t; k < NN; k += 1024) {
        int cnt  = g_cnt[k];
        int excl = g_scan[k] - cnt + g_boff[k >> 10];
        g_rowptr[k] = excl;
        g_cursor[k] = excl;
        g_deginv[k] = 1.0f / (float)max(cnt, 1);
    }
}

// ---------------- launch 2: CSR fill (+re-zero g_cnt) + W_tgt transpose --------
__global__ void __launch_bounds__(256) k_fill(const int* __restrict__ src,
                                              const int* __restrict__ tgt,
                                              const float* __restrict__ W_tgt) {
    int bid = blockIdx.x;
    int tid = threadIdx.x;
    if (bid == 6250) {
        for (int i = tid; i < DOUT*DOUT; i += 256) {
            int p = i >> 6, o = i & 63;
            g_wt[o*DOUT + p] = W_tgt[i];
        }
        return;
    }
    int e = bid*256 + tid;
    if (e < NE) {
        int p = atomicAdd(&g_cursor[tgt[e]], 1);
        g_col[p] = src[e];
    }
    if (e < NN) g_cnt[e] = 0;
}

// ---------------- launch 3: emb GEMM, smem-tiled, f32x2 (profiled window) -------
// grid (1563, 6): y = scale*2 + out-half. Block: 64 nodes x 32 outs.
// sd: data tile [64][128] XOR-swizzled (no pad; d-broadcast conflict-free).
// Thread = 1 node x 8 outs (4 f32x2 accumulators).
__global__ void __launch_bounds__(256) k_emb(const float* __restrict__ data,
                                             const float* __restrict__ Ws,
                                             const float* __restrict__ bs) {
    __shared__ float sd[64*DIN];      // 32KB
    __shared__ float sw[DIN*32];      // 16KB
    int tid = threadIdx.x;
    int s   = blockIdx.y >> 1;        // scale
    int oh  = blockIdx.y & 1;         // out-half: outs oh*32 .. oh*32+31
    int n0  = blockIdx.x * 64;

    // stage W half-tile: sw[k][c] = W[k][oh*32+c]
    {
        const float4* Wg = (const float4*)(Ws + (size_t)s*DIN*DOUT);
        float4* sw4 = (float4*)sw;
        #pragma unroll
        for (int i = tid; i < DIN*32/4; i += 256) {
            int k = i >> 3, c4 = i & 7;
            sw4[i] = Wg[k*16 + oh*8 + c4];
        }
    }
    // stage data tile, XOR-swizzled: sd[r][ (4*kq) ^ ((r&7)<<2) ] = data[n0+r][4*kq..]
    #pragma unroll
    for (int i = tid; i < 64*DIN/4; i += 256) {
        int r = i >> 5, kq = i & 31;
        int n = n0 + r;
        float4 v = (n < NN) ? __ldg(&((const float4*)data)[(size_t)n*(DIN/4) + kq])
                            : make_float4(0.f,0.f,0.f,0.f);
        int col = (kq*4) ^ ((r & 7) << 2);
        *(float4*)&sd[r*DIN + col] = v;
    }
    __syncthreads();

    int nd = tid >> 2;                // node within tile (0..63)
    int oq = tid & 3;                 // out octet: outs oq*8 .. oq*8+7 (of this half)
    int xmask = (nd & 7) << 2;
    const float* sdr = sd + nd*DIN;
    const unsigned long long* bsp =
        (const unsigned long long*)(bs + s*DOUT + oh*32 + oq*8);
    unsigned long long acc0 = bsp[0], acc1 = bsp[1], acc2 = bsp[2], acc3 = bsp[3];

    #pragma unroll 8
    for (int k = 0; k < DIN; k++) {
        unsigned long long dd = bcast2(sdr[k ^ xmask]);
        const ulonglong2* w2 = (const ulonglong2*)(sw + k*32 + oq*8);
        ulonglong2 wa = w2[0], wb = w2[1];
        acc0 = fma2(dd, wa.x, acc0);
        acc1 = fma2(dd, wa.y, acc1);
        acc2 = fma2(dd, wb.x, acc2);
        acc3 = fma2(dd, wb.y, acc3);
    }

    int n = n0 + nd;
    if (n >= NN) return;
    const float tv[NS] = {0.1f, 0.2f, 0.3f};
    float t = tv[s];
    size_t idx2 = ((size_t)n*ROW + s*DOUT + oh*32 + oq*8) >> 1;   // half2 units
    float2 f0 = unpk2(acc0), f1 = unpk2(acc1), f2 = unpk2(acc2), f3 = unpk2(acc3);
    g_hA[idx2+0] = __float22half2_rn(f0);
    g_hA[idx2+1] = __float22half2_rn(f1);
    g_hA[idx2+2] = __float22half2_rn(f2);
    g_hA[idx2+3] = __float22half2_rn(f3);
    g_temb[idx2+0] = __floats2half2_rn(t*f0.x, t*f0.y);
    g_temb[idx2+1] = __floats2half2_rn(t*f1.x, t*f1.y);
    g_temb[idx2+2] = __floats2half2_rn(t*f2.x, t*f2.y);
    g_temb[idx2+3] = __floats2half2_rn(t*f3.x, t*f3.y);
}

// ---------------- launches 4..13: propagation (R8 version: plain FADD accs) -----
__global__ void __launch_bounds__(256) k_prop(const __half2* __restrict__ xh,
                                              __half2* __restrict__ yh) {
    int w    = (blockIdx.x*blockDim.x + threadIdx.x) >> 5;
    int lane = threadIdx.x & 31;
    if (w >= NN) return;
    int beg = g_rowptr[w], end = g_rowptr[w+1];

    float a0x=0.f,a0y=0.f,a1x=0.f,a1y=0.f,a2x=0.f,a2y=0.f;

    int j = beg;
    for (; j + 4 <= end; j += 4) {
        int c0 = __ldg(&g_col[j+0]);
        int c1 = __ldg(&g_col[j+1]);
        int c2 = __ldg(&g_col[j+2]);
        int c3 = __ldg(&g_col[j+3]);
        const __half2* r0 = xh + (size_t)c0*HROW;
        const __half2* r1 = xh + (size_t)c1*HROW;
        const __half2* r2 = xh + (size_t)c2*HROW;
        const __half2* r3 = xh + (size_t)c3*HROW;
        float2 v00 = __half22float2(r0[lane]);
        float2 v10 = __half22float2(r1[lane]);
        float2 v20 = __half22float2(r2[lane]);
        float2 v30 = __half22float2(r3[lane]);
        float2 v01 = __half22float2(r0[32+lane]);
        float2 v11 = __half22float2(r1[32+lane]);
        float2 v21 = __half22float2(r2[32+lane]);
        float2 v31 = __half22float2(r3[32+lane]);
        float2 v02 = __half22float2(r0[64+lane]);
        float2 v12 = __half22float2(r1[64+lane]);
        float2 v22 = __half22float2(r2[64+lane]);
        float2 v32 = __half22float2(r3[64+lane]);
        a0x += (v00.x + v10.x) + (v20.x + v30.x);
        a0y += (v00.y + v10.y) + (v20.y + v30.y);
        a1x += (v01.x + v11.x) + (v21.x + v31.x);
        a1y += (v01.y + v11.y) + (v21.y + v31.y);
        a2x += (v02.x + v12.x) + (v22.x + v32.x);
        a2y += (v02.y + v12.y) + (v22.y + v32.y);
    }
    for (; j < end; j++) {
        int c = __ldg(&g_col[j]);
        const __half2* r = xh + (size_t)c*HROW;
        float2 v0 = __half22float2(r[lane]);
        float2 v1 = __half22float2(r[32+lane]);
        float2 v2 = __half22float2(r[64+lane]);
        a0x += v0.x; a0y += v0.y;
        a1x += v1.x; a1y += v1.y;
        a2x += v2.x; a2y += v2.y;
    }

    const __half2* tm = g_temb + (size_t)w*HROW;
    __half2* hr = yh + (size_t)w*HROW;

    if (end > beg) {
        const __half2* xo = xh + (size_t)w*HROW;
        float dinv = g_deginv[w];
        const float i0 = 0.9f, i1 = 0.8f, i2 = 0.7f;
        float2 e0 = __half22float2(tm[lane]);
        float2 e1 = __half22float2(tm[32 + lane]);
        float2 e2 = __half22float2(tm[64 + lane]);
        float2 o0 = __half22float2(xo[lane]);
        float2 o1 = __half22float2(xo[32 + lane]);
        float2 o2 = __half22float2(xo[64 + lane]);
        float2 r;
        r.x = i0*(o0.x - a0x*dinv) + e0.x;
        r.y = i0*(o0.y - a0y*dinv) + e0.y;  hr[lane]      = __float22half2_rn(r);
        r.x = i1*(o1.x - a1x*dinv) + e1.x;
        r.y = i1*(o1.y - a1y*dinv) + e1.y;  hr[32 + lane] = __float22half2_rn(r);
        r.x = i2*(o2.x - a2x*dinv) + e2.x;
        r.y = i2*(o2.y - a2y*dinv) + e2.y;  hr[64 + lane] = __float22half2_rn(r);
    } else {
        hr[lane]      = tm[lane];
        hr[32 + lane] = tm[32 + lane];
        hr[64 + lane] = tm[64 + lane];
    }
}

// ---------------- launch 14: fused attention epilogue, warp per node ------------
__global__ void __launch_bounds__(256) k_final(
        const __half2* __restrict__ xin, const float* __restrict__ data,
        const float* __restrict__ W_src, const float* __restrict__ b_src,
        const float* __restrict__ b_tgt, float* __restrict__ out) {
    __shared__ float sd[8][DIN];
    __shared__ float ssf[8][DOUT];
    int tid  = threadIdx.x;
    int wid  = tid >> 5;
    int lane = tid & 31;
    int n = blockIdx.x*8 + wid;

    float4 dv = ((const float4*)(data + (size_t)n*DIN))[lane];
    ((float4*)sd[wid])[lane] = dv;
    __syncthreads();

    const float2* ws2 = (const float2*)W_src;
    float2 bsv = ((const float2*)b_src)[lane];
    float a0 = bsv.x, a1 = bsv.y;
    #pragma unroll 8
    for (int k = 0; k < DIN; k++) {
        float d = sd[wid][k];
        float2 wv = ws2[k*32 + lane];
        a0 += d * wv.x;
        a1 += d * wv.y;
    }
    ssf[wid][2*lane]     = a0;
    ssf[wid][2*lane + 1] = a1;
    __syncwarp();

    const __half2* xr = xin + (size_t)n*HROW;
    float sc[NS][2];
    #pragma unroll
    for (int s = 0; s < NS; s++) {
        float2 v = __half22float2(xr[s*32 + lane]);
        sc[s][0] = fmaxf(v.x, 0.f);
        sc[s][1] = fmaxf(v.y, 0.f);
    }

    const float2* wt2 = (const float2*)g_wt;
    float u0 = 0.f, u1 = 0.f;
    #pragma unroll 8
    for (int o = 0; o < DOUT; o++) {
        float sa = ssf[wid][o];
        float2 wv = __ldg(&wt2[o*32 + lane]);
        u0 += wv.x * sa;
        u1 += wv.y * sa;
    }

    float2 btv = ((const float2*)b_tgt)[lane];
    float cp = btv.x*a0 + btv.y*a1;
    for (int m = 16; m; m >>= 1) cp += __shfl_xor_sync(0xffffffffu, cp, m);

    float lg[NS];
    #pragma unroll
    for (int s = 0; s < NS; s++) {
        float p = sc[s][0]*u0 + sc[s][1]*u1;
        for (int m = 16; m; m >>= 1) p += __shfl_xor_sync(0xffffffffu, p, m);
        lg[s] = p + cp;
    }

    float mx = fmaxf(lg[0], fmaxf(lg[1], lg[2]));
    float e0 = expf(lg[0]-mx), e1 = expf(lg[1]-mx), e2 = expf(lg[2]-mx);
    float inv = 1.f / (e0 + e1 + e2);
    float w0 = e0*inv, w1 = e1*inv, w2 = e2*inv;

    float2 ov;
    ov.x = w0*sc[0][0] + w1*sc[1][0] + w2*sc[2][0];
    ov.y = w0*sc[0][1] + w1*sc[1][1] + w2*sc[2][1];
    ((float2*)out)[(size_t)n*32 + lane] = ov;
}

// ---------------- launch ----------------
extern "C" void kernel_launch(void* const* d_in, const int* in_sizes, int n_in,
                              void* d_out, int out_size) {
    const float* data  = (const float*)d_in[0];
    const int*   src   = (const int*)  d_in[1];
    const int*   tgt   = (const int*)  d_in[2];
    const float* Ws    = (const float*)d_in[3];
    const float* bs    = (const float*)d_in[4];
    const float* W_src = (const float*)d_in[5];
    const float* b_src = (const float*)d_in[6];
    const float* W_tgt = (const float*)d_in[7];
    const float* b_tgt = (const float*)d_in[8];
    float* out = (float*)d_out;

    k_hist<<<(NE+255)/256, 256>>>(tgt);            // launch 0
    k_scan<<<(NN+1023)/1024, 1024>>>();            // launch 1
    k_fill<<<6251, 256>>>(src, tgt, W_tgt);        // launch 2
    dim3 ge((NN + 63)/64, NS*2);
    k_emb<<<ge, 256>>>(data, Ws, bs);              // launch 3 (profiled)

    __half2 *hA, *hB;
    cudaGetSymbolAddress((void**)&hA, g_hA);
    cudaGetSymbolAddress((void**)&hB, g_hB);

    const __half2* cur = hA;
    __half2*       nxt = hB;
    for (int d = 0; d < DEPTH; d++) {              // launches 4..13
        k_prop<<<NN/8, 256>>>(cur, nxt);
        const __half2* tmp = nxt;
        nxt = (__half2*)cur;
        cur = tmp;
    }

    k_final<<<NN/8, 256>>>(cur, data, W_src, b_src, b_tgt, out);   // launch 14
}

// round 11
// speedup vs baseline: 1.3332x; 1.2054x over previous
#include <cuda_runtime.h>
#include <cuda_fp16.h>

#define NN 100000
#define NE 1600000
#define NS 3
#define DIN 128
#define DOUT 64
#define ROW (NS*DOUT)    /* 192 halfs per node state row */
#define HROW 96          /* 96 half2 per node row */
#define DEPTH 10

// ---------------- device scratch (static: no allocation allowed) ----------------
__device__ __half2 g_hA  [NN*HROW];    // fp16 state (double buffered)
__device__ __half2 g_hB  [NN*HROW];
__device__ __half2 g_temb[NN*HROW];    // fp16 t*emb (teleport term)
__device__ float   g_wt  [DOUT*DOUT];  // W_tgt transposed
__device__ int     g_cnt[NN];
__device__ int     g_rowptr[NN+1];
__device__ int     g_cursor[NN];
__device__ float   g_deginv[NN];
__device__ int     g_col[NE];
__device__ int     g_scan[NN];
__device__ int     g_bsum[128];
__device__ int     g_boff[128];
__device__ int     g_done;

// f32x2 helpers (FFMA2 only reachable via PTX)
__device__ __forceinline__ unsigned long long fma2(unsigned long long a,
                                                   unsigned long long b,
                                                   unsigned long long c) {
    unsigned long long r;
    asm("fma.rn.f32x2 %0, %1, %2, %3;" : "=l"(r) : "l"(a), "l"(b), "l"(c));
    return r;
}
__device__ __forceinline__ unsigned long long bcast2(float x) {
    unsigned long long r;
    asm("mov.b64 %0, {%1, %1};" : "=l"(r) : "f"(x));
    return r;
}
__device__ __forceinline__ float2 unpk2(unsigned long long a) {
    float2 v;
    asm("mov.b64 {%0, %1}, %2;" : "=f"(v.x), "=f"(v.y) : "l"(a));
    return v;
}

// ---------------- launch 0: histogram ----------------
__global__ void k_hist(const int* __restrict__ tgt) {
    int e = blockIdx.x*blockDim.x + threadIdx.x;
    if (e < NE) atomicAdd(&g_cnt[tgt[e]], 1);
}

// ---------------- launch 1: fused scan (decoupled last-block finish) ----------
__global__ void k_scan() {
    __shared__ int sh[1024];
    __shared__ bool s_last;
    int t = threadIdx.x;
    int i = blockIdx.x*1024 + t;
    int v = (i < NN) ? g_cnt[i] : 0;
    sh[t] = v;
    __syncthreads();
    for (int off = 1; off < 1024; off <<= 1) {
        int add = (t >= off) ? sh[t-off] : 0;
        __syncthreads();
        sh[t] += add;
        __syncthreads();
    }
    if (i < NN) g_scan[i] = sh[t];
    if (t == 1023) g_bsum[blockIdx.x] = sh[1023];
    __threadfence();
    if (t == 0) {
        int done = atomicAdd(&g_done, 1);
        s_last = (done == (int)gridDim.x - 1);
    }
    __syncthreads();
    if (!s_last) return;
    __threadfence();
    if (t == 0) {
        int run = 0;
        for (int b = 0; b < (int)gridDim.x; b++) { g_boff[b] = run; run += g_bsum[b]; }
        g_done = 0;
        g_rowptr[NN] = NE;
    }
    __syncthreads();
    for (int k = t; k < NN; k += 1024) {
        int cnt  = g_cnt[k];
        int excl = g_scan[k] - cnt + g_boff[k >> 10];
        g_rowptr[k] = excl;
        g_cursor[k] = excl;
        g_deginv[k] = 1.0f / (float)max(cnt, 1);
    }
}

// ---------------- launch 2: CSR fill (+re-zero g_cnt) + W_tgt transpose --------
__global__ void __launch_bounds__(256) k_fill(const int* __restrict__ src,
                                              const int* __restrict__ tgt,
                                              const float* __restrict__ W_tgt) {
    int bid = blockIdx.x;
    int tid = threadIdx.x;
    if (bid == 6250) {
        for (int i = tid; i < DOUT*DOUT; i += 256) {
            int p = i >> 6, o = i & 63;
            g_wt[o*DOUT + p] = W_tgt[i];
        }
        return;
    }
    int e = bid*256 + tid;
    if (e < NE) {
        int p = atomicAdd(&g_cursor[tgt[e]], 1);
        g_col[p] = src[e];
    }
    if (e < NN) g_cnt[e] = 0;
}

// ---------------- launch 3: emb GEMM v3 (profiled window) -----------------------
// grid (1563, NS). Block = 64 nodes x 64 outs; thread = 4 nodes x 4 outs.
// sw: full W tile [128][64] (32KB). sd: 64-k half tile [64][64] staged twice (16KB).
// Per k-quad/thread: 4 d-LDS.128 + 4 w-LDS.128 = 128B feeding 32 FFMA2 (4B/FFMA2).
__global__ void __launch_bounds__(256) k_emb(const float* __restrict__ data,
                                             const float* __restrict__ Ws,
                                             const float* __restrict__ bs) {
    __shared__ float sw[DIN*DOUT];    // 32KB: sw[k][o]
    __shared__ float sd[64*64];       // 16KB: half-k tile, chunk-XOR swizzled
    int tid = threadIdx.x;
    int s   = blockIdx.y;
    int n0  = blockIdx.x * 64;

    // stage full W tile (layout identical to global, coalesced float4)
    {
        const float4* Wg = (const float4*)(Ws + (size_t)s*DIN*DOUT);
        float4* sw4 = (float4*)sw;
        #pragma unroll
        for (int i = tid; i < DIN*DOUT/4; i += 256) sw4[i] = __ldg(&Wg[i]);
    }

    int nd4 = tid >> 4;               // node quad (0..15): nodes nd4*4..+3
    int oq  = tid & 15;               // out quad  (0..15): outs  oq*4..+3
    const unsigned long long* bsp =
        (const unsigned long long*)(bs + s*DOUT + oq*4);
    unsigned long long acc[4][2];
    {
        unsigned long long b01 = bsp[0], b23 = bsp[1];
        #pragma unroll
        for (int i = 0; i < 4; i++) { acc[i][0] = b01; acc[i][1] = b23; }
    }

    const float4* data4 = (const float4*)data;
    #pragma unroll
    for (int half = 0; half < 2; half++) {
        __syncthreads();              // protect sd from previous half's readers
        #pragma unroll
        for (int it = 0; it < 4; it++) {
            int i = it*256 + tid;
            int r = i >> 4, c = i & 15;
            int n = n0 + r;
            float4 v = (n < NN) ? __ldg(&data4[(size_t)n*32 + half*16 + c])
                                : make_float4(0.f, 0.f, 0.f, 0.f);
            *(float4*)&sd[r*64 + ((c ^ (r & 7)) << 2)] = v;
        }
        __syncthreads();

        #pragma unroll 4
        for (int k4 = 0; k4 < 16; k4++) {
            float4 dv[4];
            #pragma unroll
            for (int i = 0; i < 4; i++) {
                int r = nd4*4 + i;
                dv[i] = *(const float4*)&sd[r*64 + ((k4 ^ (r & 7)) << 2)];
            }
            #pragma unroll
            for (int j = 0; j < 4; j++) {
                int k = half*64 + k4*4 + j;
                ulonglong2 w = *(const ulonglong2*)&sw[k*DOUT + (oq << 2)];
                #pragma unroll
                for (int i = 0; i < 4; i++) {
                    unsigned long long db = bcast2(((const float*)&dv[i])[j]);
                    acc[i][0] = fma2(db, w.x, acc[i][0]);
                    acc[i][1] = fma2(db, w.y, acc[i][1]);
                }
            }
        }
    }

    const float tv[NS] = {0.1f, 0.2f, 0.3f};
    float t = tv[s];
    #pragma unroll
    for (int i = 0; i < 4; i++) {
        int n = n0 + nd4*4 + i;
        if (n >= NN) continue;
        float2 f0 = unpk2(acc[i][0]), f1 = unpk2(acc[i][1]);
        size_t idx2 = ((size_t)n*ROW + s*DOUT + oq*4) >> 1;   // half2 units
        g_hA[idx2]     = __float22half2_rn(f0);
        g_hA[idx2 + 1] = __float22half2_rn(f1);
        g_temb[idx2]     = __floats2half2_rn(t*f0.x, t*f0.y);
        g_temb[idx2 + 1] = __floats2half2_rn(t*f1.x, t*f1.y);
    }
}

// ---------------- launches 4..13: propagation (plain FADD accs; 62us/step) ------
__global__ void __launch_bounds__(256) k_prop(const __half2* __restrict__ xh,
                                              __half2* __restrict__ yh) {
    int w    = (blockIdx.x*blockDim.x + threadIdx.x) >> 5;
    int lane = threadIdx.x & 31;
    if (w >= NN) return;
    int beg = g_rowptr[w], end = g_rowptr[w+1];

    float a0x=0.f,a0y=0.f,a1x=0.f,a1y=0.f,a2x=0.f,a2y=0.f;

    int j = beg;
    for (; j + 4 <= end; j += 4) {
        int c0 = __ldg(&g_col[j+0]);
        int c1 = __ldg(&g_col[j+1]);
        int c2 = __ldg(&g_col[j+2]);
        int c3 = __ldg(&g_col[j+3]);
        const __half2* r0 = xh + (size_t)c0*HROW;
        const __half2* r1 = xh + (size_t)c1*HROW;
        const __half2* r2 = xh + (size_t)c2*HROW;
        const __half2* r3 = xh + (size_t)c3*HROW;
        float2 v00 = __half22float2(r0[lane]);
        float2 v10 = __half22float2(r1[lane]);
        float2 v20 = __half22float2(r2[lane]);
        float2 v30 = __half22float2(r3[lane]);
        float2 v01 = __half22float2(r0[32+lane]);
        float2 v11 = __half22float2(r1[32+lane]);
        float2 v21 = __half22float2(r2[32+lane]);
        float2 v31 = __half22float2(r3[32+lane]);
        float2 v02 = __half22float2(r0[64+lane]);
        float2 v12 = __half22float2(r1[64+lane]);
        float2 v22 = __half22float2(r2[64+lane]);
        float2 v32 = __half22float2(r3[64+lane]);
        a0x += (v00.x + v10.x) + (v20.x + v30.x);
        a0y += (v00.y + v10.y) + (v20.y + v30.y);
        a1x += (v01.x + v11.x) + (v21.x + v31.x);
        a1y += (v01.y + v11.y) + (v21.y + v31.y);
        a2x += (v02.x + v12.x) + (v22.x + v32.x);
        a2y += (v02.y + v12.y) + (v22.y + v32.y);
    }
    for (; j < end; j++) {
        int c = __ldg(&g_col[j]);
        const __half2* r = xh + (size_t)c*HROW;
        float2 v0 = __half22float2(r[lane]);
        float2 v1 = __half22float2(r[32+lane]);
        float2 v2 = __half22float2(r[64+lane]);
        a0x += v0.x; a0y += v0.y;
        a1x += v1.x; a1y += v1.y;
        a2x += v2.x; a2y += v2.y;
    }

    const __half2* tm = g_temb + (size_t)w*HROW;
    __half2* hr = yh + (size_t)w*HROW;

    if (end > beg) {
        const __half2* xo = xh + (size_t)w*HROW;
        float dinv = g_deginv[w];
        const float i0 = 0.9f, i1 = 0.8f, i2 = 0.7f;
        float2 e0 = __half22float2(tm[lane]);
        float2 e1 = __half22float2(tm[32 + lane]);
        float2 e2 = __half22float2(tm[64 + lane]);
        float2 o0 = __half22float2(xo[lane]);
        float2 o1 = __half22float2(xo[32 + lane]);
        float2 o2 = __half22float2(xo[64 + lane]);
        float2 r;
        r.x = i0*(o0.x - a0x*dinv) + e0.x;
        r.y = i0*(o0.y - a0y*dinv) + e0.y;  hr[lane]      = __float22half2_rn(r);
        r.x = i1*(o1.x - a1x*dinv) + e1.x;
        r.y = i1*(o1.y - a1y*dinv) + e1.y;  hr[32 + lane] = __float22half2_rn(r);
        r.x = i2*(o2.x - a2x*dinv) + e2.x;
        r.y = i2*(o2.y - a2y*dinv) + e2.y;  hr[64 + lane] = __float22half2_rn(r);
    } else {
        hr[lane]      = tm[lane];
        hr[32 + lane] = tm[32 + lane];
        hr[64 + lane] = tm[64 + lane];
    }
}

// ---------------- launch 14: fused attention epilogue, warp per node ------------
__global__ void __launch_bounds__(256) k_final(
        const __half2* __restrict__ xin, const float* __restrict__ data,
        const float* __restrict__ W_src, const float* __restrict__ b_src,
        const float* __restrict__ b_tgt, float* __restrict__ out) {
    __shared__ float sd[8][DIN];
    __shared__ float ssf[8][DOUT];
    int tid  = threadIdx.x;
    int wid  = tid >> 5;
    int lane = tid & 31;
    int n = blockIdx.x*8 + wid;

    float4 dv = ((const float4*)(data + (size_t)n*DIN))[lane];
    ((float4*)sd[wid])[lane] = dv;
    __syncthreads();

    const float2* ws2 = (const float2*)W_src;
    float2 bsv = ((const float2*)b_src)[lane];
    float a0 = bsv.x, a1 = bsv.y;
    #pragma unroll 8
    for (int k = 0; k < DIN; k++) {
        float d = sd[wid][k];
        float2 wv = ws2[k*32 + lane];
        a0 += d * wv.x;
        a1 += d * wv.y;
    }
    ssf[wid][2*lane]     = a0;
    ssf[wid][2*lane + 1] = a1;
    __syncwarp();

    const __half2* xr = xin + (size_t)n*HROW;
    float sc[NS][2];
    #pragma unroll
    for (int s = 0; s < NS; s++) {
        float2 v = __half22float2(xr[s*32 + lane]);
        sc[s][0] = fmaxf(v.x, 0.f);
        sc[s][1] = fmaxf(v.y, 0.f);
    }

    const float2* wt2 = (const float2*)g_wt;
    float u0 = 0.f, u1 = 0.f;
    #pragma unroll 8
    for (int o = 0; o < DOUT; o++) {
        float sa = ssf[wid][o];
        float2 wv = __ldg(&wt2[o*32 + lane]);
        u0 += wv.x * sa;
        u1 += wv.y * sa;
    }

    float2 btv = ((const float2*)b_tgt)[lane];
    float cp = btv.x*a0 + btv.y*a1;
    for (int m = 16; m; m >>= 1) cp += __shfl_xor_sync(0xffffffffu, cp, m);

    float lg[NS];
    #pragma unroll
    for (int s = 0; s < NS; s++) {
        float p = sc[s][0]*u0 + sc[s][1]*u1;
        for (int m = 16; m; m >>= 1) p += __shfl_xor_sync(0xffffffffu, p, m);
        lg[s] = p + cp;
    }

    float mx = fmaxf(lg[0], fmaxf(lg[1], lg[2]));
    float e0 = expf(lg[0]-mx), e1 = expf(lg[1]-mx), e2 = expf(lg[2]-mx);
    float inv = 1.f / (e0 + e1 + e2);
    float w0 = e0*inv, w1 = e1*inv, w2 = e2*inv;

    float2 ov;
    ov.x = w0*sc[0][0] + w1*sc[1][0] + w2*sc[2][0];
    ov.y = w0*sc[0][1] + w1*sc[1][1] + w2*sc[2][1];
    ((float2*)out)[(size_t)n*32 + lane] = ov;
}

// ---------------- launch ----------------
extern "C" void kernel_launch(void* const* d_in, const int* in_sizes, int n_in,
                              void* d_out, int out_size) {
    const float* data  = (const float*)d_in[0];
    const int*   src   = (const int*)  d_in[1];
    const int*   tgt   = (const int*)  d_in[2];
    const float* Ws    = (const float*)d_in[3];
    const float* bs    = (const float*)d_in[4];
    const float* W_src = (const float*)d_in[5];
    const float* b_src = (const float*)d_in[6];
    const float* W_tgt = (const float*)d_in[7];
    const float* b_tgt = (const float*)d_in[8];
    float* out = (float*)d_out;

    k_hist<<<(NE+255)/256, 256>>>(tgt);            // launch 0
    k_scan<<<(NN+1023)/1024, 1024>>>();            // launch 1
    k_fill<<<6251, 256>>>(src, tgt, W_tgt);        // launch 2
    dim3 ge((NN + 63)/64, NS);
    k_emb<<<ge, 256>>>(data, Ws, bs);              // launch 3 (profiled)

    __half2 *hA, *hB;
    cudaGetSymbolAddress((void**)&hA, g_hA);
    cudaGetSymbolAddress((void**)&hB, g_hB);

    const __half2* cur = hA;
    __half2*       nxt = hB;
    for (int d = 0; d < DEPTH; d++) {              // launches 4..13
        k_prop<<<NN/8, 256>>>(cur, nxt);
        const __half2* tmp = nxt;
        nxt = (__half2*)cur;
        cur = tmp;
    }

    k_final<<<NN/8, 256>>>(cur, data, W_src, b_src, b_tgt, out);   // launch 14
}

// round 12
// speedup vs baseline: 1.4442x; 1.0832x over previous
#include <cuda_runtime.h>
#include <cuda_fp16.h>

#define NN 100000
#define NE 1600000
#define NS 3
#define DIN 128
#define DOUT 64
#define ROW (NS*DOUT)    /* 192 halfs per node state row */
#define HROW 96          /* 96 half2 per node row */
#define DEPTH 10

// ---------------- device scratch (static: no allocation allowed) ----------------
__device__ __half2 g_hA  [NN*HROW];    // fp16 state (double buffered)
__device__ __half2 g_hB  [NN*HROW];
__device__ __half2 g_temb[NN*HROW];    // fp16 t*emb (teleport term)
__device__ float   g_satt[NN*DOUT];    // fp32 s_att = data@W_src + b_src
__device__ float   g_wt  [DOUT*DOUT];  // W_tgt transposed
__device__ int     g_cnt[NN];
__device__ int     g_rowptr[NN+1];
__device__ int     g_cursor[NN];
__device__ float   g_deginv[NN];
__device__ int     g_col[NE];
__device__ int     g_scan[NN];
__device__ int     g_bsum[128];
__device__ int     g_boff[128];
__device__ int     g_done;

// f32x2 helpers (FFMA2 only reachable via PTX)
__device__ __forceinline__ unsigned long long fma2(unsigned long long a,
                                                   unsigned long long b,
                                                   unsigned long long c) {
    unsigned long long r;
    asm("fma.rn.f32x2 %0, %1, %2, %3;" : "=l"(r) : "l"(a), "l"(b), "l"(c));
    return r;
}
__device__ __forceinline__ unsigned long long bcast2(float x) {
    unsigned long long r;
    asm("mov.b64 %0, {%1, %1};" : "=l"(r) : "f"(x));
    return r;
}
__device__ __forceinline__ float2 unpk2(unsigned long long a) {
    float2 v;
    asm("mov.b64 {%0, %1}, %2;" : "=f"(v.x), "=f"(v.y) : "l"(a));
    return v;
}

// ---------------- launch 0: histogram ----------------
__global__ void k_hist(const int* __restrict__ tgt) {
    int e = blockIdx.x*blockDim.x + threadIdx.x;
    if (e < NE) atomicAdd(&g_cnt[tgt[e]], 1);
}

// ---------------- launch 1: fused scan (decoupled last-block finish) ----------
__global__ void k_scan() {
    __shared__ int sh[1024];
    __shared__ bool s_last;
    int t = threadIdx.x;
    int i = blockIdx.x*1024 + t;
    int v = (i < NN) ? g_cnt[i] : 0;
    sh[t] = v;
    __syncthreads();
    for (int off = 1; off < 1024; off <<= 1) {
        int add = (t >= off) ? sh[t-off] : 0;
        __syncthreads();
        sh[t] += add;
        __syncthreads();
    }
    if (i < NN) g_scan[i] = sh[t];
    if (t == 1023) g_bsum[blockIdx.x] = sh[1023];
    __threadfence();
    if (t == 0) {
        int done = atomicAdd(&g_done, 1);
        s_last = (done == (int)gridDim.x - 1);
    }
    __syncthreads();
    if (!s_last) return;
    __threadfence();
    if (t == 0) {
        int run = 0;
        for (int b = 0; b < (int)gridDim.x; b++) { g_boff[b] = run; run += g_bsum[b]; }
        g_done = 0;
        g_rowptr[NN] = NE;
    }
    __syncthreads();
    for (int k = t; k < NN; k += 1024) {
        int cnt  = g_cnt[k];
        int excl = g_scan[k] - cnt + g_boff[k >> 10];
        g_rowptr[k] = excl;
        g_cursor[k] = excl;
        g_deginv[k] = 1.0f / (float)max(cnt, 1);
    }
}

// ---------------- launch 2: CSR fill (+re-zero g_cnt) + W_tgt transpose --------
__global__ void __launch_bounds__(256) k_fill(const int* __restrict__ src,
                                              const int* __restrict__ tgt,
                                              const float* __restrict__ W_tgt) {
    int bid = blockIdx.x;
    int tid = threadIdx.x;
    if (bid == 6250) {
        for (int i = tid; i < DOUT*DOUT; i += 256) {
            int p = i >> 6, o = i & 63;
            g_wt[o*DOUT + p] = W_tgt[i];
        }
        return;
    }
    int e = bid*256 + tid;
    if (e < NE) {
        int p = atomicAdd(&g_cursor[tgt[e]], 1);
        g_col[p] = src[e];
    }
    if (e < NN) g_cnt[e] = 0;
}

// ---------------- launch 3: tiled GEMM — 3 emb slices + s_att slice -------------
// grid (1563, 4). y<3: emb scale y; y==3: s_att = data@W_src + b_src (fp32 out).
// Block = 64 nodes x 64 outs; thread = 4 nodes x 4 outs (f32x2 FFMA2).
__global__ void __launch_bounds__(256) k_emb(const float* __restrict__ data,
                                             const float* __restrict__ Ws,
                                             const float* __restrict__ bs,
                                             const float* __restrict__ W_src,
                                             const float* __restrict__ b_src) {
    __shared__ float sw[DIN*DOUT];    // 32KB: sw[k][o]
    __shared__ float sd[64*64];       // 16KB: half-k tile, chunk-XOR swizzled
    int tid = threadIdx.x;
    int s   = blockIdx.y;             // 0..3
    int n0  = blockIdx.x * 64;

    const float* Wp = (s < NS) ? (Ws + (size_t)s*DIN*DOUT) : W_src;
    const float* bp = (s < NS) ? (bs + s*DOUT)             : b_src;

    {
        const float4* Wg = (const float4*)Wp;
        float4* sw4 = (float4*)sw;
        #pragma unroll
        for (int i = tid; i < DIN*DOUT/4; i += 256) sw4[i] = __ldg(&Wg[i]);
    }

    int nd4 = tid >> 4;               // node quad (0..15)
    int oq  = tid & 15;               // out quad (0..15)
    const unsigned long long* bsp = (const unsigned long long*)(bp + oq*4);
    unsigned long long acc[4][2];
    {
        unsigned long long b01 = bsp[0], b23 = bsp[1];
        #pragma unroll
        for (int i = 0; i < 4; i++) { acc[i][0] = b01; acc[i][1] = b23; }
    }

    const float4* data4 = (const float4*)data;
    #pragma unroll
    for (int half = 0; half < 2; half++) {
        __syncthreads();
        #pragma unroll
        for (int it = 0; it < 4; it++) {
            int i = it*256 + tid;
            int r = i >> 4, c = i & 15;
            int n = n0 + r;
            float4 v = (n < NN) ? __ldg(&data4[(size_t)n*32 + half*16 + c])
                                : make_float4(0.f, 0.f, 0.f, 0.f);
            *(float4*)&sd[r*64 + ((c ^ (r & 7)) << 2)] = v;
        }
        __syncthreads();

        #pragma unroll 4
        for (int k4 = 0; k4 < 16; k4++) {
            float4 dv[4];
            #pragma unroll
            for (int i = 0; i < 4; i++) {
                int r = nd4*4 + i;
                dv[i] = *(const float4*)&sd[r*64 + ((k4 ^ (r & 7)) << 2)];
            }
            #pragma unroll
            for (int j = 0; j < 4; j++) {
                int k = half*64 + k4*4 + j;
                ulonglong2 w = *(const ulonglong2*)&sw[k*DOUT + (oq << 2)];
                #pragma unroll
                for (int i = 0; i < 4; i++) {
                    unsigned long long db = bcast2(((const float*)&dv[i])[j]);
                    acc[i][0] = fma2(db, w.x, acc[i][0]);
                    acc[i][1] = fma2(db, w.y, acc[i][1]);
                }
            }
        }
    }

    if (s < NS) {
        const float tv[NS] = {0.1f, 0.2f, 0.3f};
        float t = tv[s];
        #pragma unroll
        for (int i = 0; i < 4; i++) {
            int n = n0 + nd4*4 + i;
            if (n >= NN) continue;
            float2 f0 = unpk2(acc[i][0]), f1 = unpk2(acc[i][1]);
            size_t idx2 = ((size_t)n*ROW + s*DOUT + oq*4) >> 1;
            g_hA[idx2]     = __float22half2_rn(f0);
            g_hA[idx2 + 1] = __float22half2_rn(f1);
            g_temb[idx2]     = __floats2half2_rn(t*f0.x, t*f0.y);
            g_temb[idx2 + 1] = __floats2half2_rn(t*f1.x, t*f1.y);
        }
    } else {
        #pragma unroll
        for (int i = 0; i < 4; i++) {
            int n = n0 + nd4*4 + i;
            if (n >= NN) continue;
            float2 f0 = unpk2(acc[i][0]), f1 = unpk2(acc[i][1]);
            *(float4*)&g_satt[(size_t)n*DOUT + oq*4] =
                make_float4(f0.x, f0.y, f1.x, f1.y);
        }
    }
}

// ---------------- launches 4..13: propagation ------------------------------------
// Pairwise HADD2 pre-reduction (1 fp16 rounding per neighbor pair, rms ~1.4e-4 of
// the pair -> negligible on the 16-mean) + aligned int4 index loads.
__global__ void __launch_bounds__(256) k_prop(const __half2* __restrict__ xh,
                                              __half2* __restrict__ yh) {
    int w    = (blockIdx.x*blockDim.x + threadIdx.x) >> 5;
    int lane = threadIdx.x & 31;
    int beg = g_rowptr[w], end = g_rowptr[w+1];

    float a0x=0.f,a0y=0.f,a1x=0.f,a1y=0.f,a2x=0.f,a2y=0.f;

    int j = beg;
    // prologue to 16B-align the index pointer
    for (; j < end && (j & 3); j++) {
        int c = __ldg(&g_col[j]);
        const __half2* r = xh + (size_t)c*HROW;
        float2 v0 = __half22float2(r[lane]);
        float2 v1 = __half22float2(r[32+lane]);
        float2 v2 = __half22float2(r[64+lane]);
        a0x += v0.x; a0y += v0.y;
        a1x += v1.x; a1y += v1.y;
        a2x += v2.x; a2y += v2.y;
    }
    for (; j + 4 <= end; j += 4) {
        int4 c = __ldg((const int4*)&g_col[j]);
        const __half2* r0 = xh + (size_t)c.x*HROW;
        const __half2* r1 = xh + (size_t)c.y*HROW;
        const __half2* r2 = xh + (size_t)c.z*HROW;
        const __half2* r3 = xh + (size_t)c.w*HROW;
        // group 0
        __half2 s01 = __hadd2(r0[lane],    r1[lane]);
        __half2 s23 = __hadd2(r2[lane],    r3[lane]);
        float2 f01 = __half22float2(s01), f23 = __half22float2(s23);
        a0x += f01.x + f23.x; a0y += f01.y + f23.y;
        // group 1
        s01 = __hadd2(r0[32+lane], r1[32+lane]);
        s23 = __hadd2(r2[32+lane], r3[32+lane]);
        f01 = __half22float2(s01); f23 = __half22float2(s23);
        a1x += f01.x + f23.x; a1y += f01.y + f23.y;
        // group 2
        s01 = __hadd2(r0[64+lane], r1[64+lane]);
        s23 = __hadd2(r2[64+lane], r3[64+lane]);
        f01 = __half22float2(s01); f23 = __half22float2(s23);
        a2x += f01.x + f23.x; a2y += f01.y + f23.y;
    }
    for (; j < end; j++) {
        int c = __ldg(&g_col[j]);
        const __half2* r = xh + (size_t)c*HROW;
        float2 v0 = __half22float2(r[lane]);
        float2 v1 = __half22float2(r[32+lane]);
        float2 v2 = __half22float2(r[64+lane]);
        a0x += v0.x; a0y += v0.y;
        a1x += v1.x; a1y += v1.y;
        a2x += v2.x; a2y += v2.y;
    }

    const __half2* tm = g_temb + (size_t)w*HROW;
    __half2* hr = yh + (size_t)w*HROW;

    if (end > beg) {
        const __half2* xo = xh + (size_t)w*HROW;
        float dinv = g_deginv[w];
        const float i0 = 0.9f, i1 = 0.8f, i2 = 0.7f;
        float2 e0 = __half22float2(tm[lane]);
        float2 e1 = __half22float2(tm[32 + lane]);
        float2 e2 = __half22float2(tm[64 + lane]);
        float2 o0 = __half22float2(xo[lane]);
        float2 o1 = __half22float2(xo[32 + lane]);
        float2 o2 = __half22float2(xo[64 + lane]);
        float2 r;
        r.x = i0*(o0.x - a0x*dinv) + e0.x;
        r.y = i0*(o0.y - a0y*dinv) + e0.y;  hr[lane]      = __float22half2_rn(r);
        r.x = i1*(o1.x - a1x*dinv) + e1.x;
        r.y = i1*(o1.y - a1y*dinv) + e1.y;  hr[32 + lane] = __float22half2_rn(r);
        r.x = i2*(o2.x - a2x*dinv) + e2.x;
        r.y = i2*(o2.y - a2y*dinv) + e2.y;  hr[64 + lane] = __float22half2_rn(r);
    } else {
        hr[lane]      = tm[lane];
        hr[32 + lane] = tm[32 + lane];
        hr[64 + lane] = tm[64 + lane];
    }
}

// ---------------- launch 14: attention epilogue (s_att precomputed) --------------
__global__ void __launch_bounds__(256) k_final(
        const __half2* __restrict__ xin,
        const float* __restrict__ b_tgt, float* __restrict__ out) {
    __shared__ float ssf[8][DOUT];
    int tid  = threadIdx.x;
    int wid  = tid >> 5;
    int lane = tid & 31;
    int n = blockIdx.x*8 + wid;

    // s_att pair (p = 2*lane, 2*lane+1) from precomputed global
    float2 sa = ((const float2*)g_satt)[(size_t)n*32 + lane];
    ssf[wid][2*lane]     = sa.x;
    ssf[wid][2*lane + 1] = sa.y;
    __syncwarp();

    // scales = relu(state), pair layout
    const __half2* xr = xin + (size_t)n*HROW;
    float sc[NS][2];
    #pragma unroll
    for (int s = 0; s < NS; s++) {
        float2 v = __half22float2(xr[s*32 + lane]);
        sc[s][0] = fmaxf(v.x, 0.f);
        sc[s][1] = fmaxf(v.y, 0.f);
    }

    // u[p] via pre-transposed W_tgt (16KB, L1-resident)
    const float2* wt2 = (const float2*)g_wt;
    float u0 = 0.f, u1 = 0.f;
    #pragma unroll 8
    for (int o = 0; o < DOUT; o++) {
        float s = ssf[wid][o];
        float2 wv = __ldg(&wt2[o*32 + lane]);
        u0 += wv.x * s;
        u1 += wv.y * s;
    }

    float2 btv = ((const float2*)b_tgt)[lane];
    float cp = btv.x*sa.x + btv.y*sa.y;
    for (int m = 16; m; m >>= 1) cp += __shfl_xor_sync(0xffffffffu, cp, m);

    float lg[NS];
    #pragma unroll
    for (int s = 0; s < NS; s++) {
        float p = sc[s][0]*u0 + sc[s][1]*u1;
        for (int m = 16; m; m >>= 1) p += __shfl_xor_sync(0xffffffffu, p, m);
        lg[s] = p + cp;
    }

    float mx = fmaxf(lg[0], fmaxf(lg[1], lg[2]));
    float e0 = expf(lg[0]-mx), e1 = expf(lg[1]-mx), e2 = expf(lg[2]-mx);
    float inv = 1.f / (e0 + e1 + e2);
    float w0 = e0*inv, w1 = e1*inv, w2 = e2*inv;

    float2 ov;
    ov.x = w0*sc[0][0] + w1*sc[1][0] + w2*sc[2][0];
    ov.y = w0*sc[0][1] + w1*sc[1][1] + w2*sc[2][1];
    ((float2*)out)[(size_t)n*32 + lane] = ov;
}

// ---------------- launch ----------------
extern "C" void kernel_launch(void* const* d_in, const int* in_sizes, int n_in,
                              void* d_out, int out_size) {
    const float* data  = (const float*)d_in[0];
    const int*   src   = (const int*)  d_in[1];
    const int*   tgt   = (const int*)  d_in[2];
    const float* Ws    = (const float*)d_in[3];
    const float* bs    = (const float*)d_in[4];
    const float* W_src = (const float*)d_in[5];
    const float* b_src = (const float*)d_in[6];
    const float* W_tgt = (const float*)d_in[7];
    const float* b_tgt = (const float*)d_in[8];
    float* out = (float*)d_out;

    k_hist<<<(NE+255)/256, 256>>>(tgt);            // launch 0
    k_scan<<<(NN+1023)/1024, 1024>>>();            // launch 1
    k_fill<<<6251, 256>>>(src, tgt, W_tgt);        // launch 2
    dim3 ge((NN + 63)/64, NS + 1);
    k_emb<<<ge, 256>>>(data, Ws, bs, W_src, b_src);  // launch 3 (profiled)

    __half2 *hA, *hB;
    cudaGetSymbolAddress((void**)&hA, g_hA);
    cudaGetSymbolAddress((void**)&hB, g_hB);

    const __half2* cur = hA;
    __half2*       nxt = hB;
    for (int d = 0; d < DEPTH; d++) {              // launches 4..13
        k_prop<<<NN/8, 256>>>(cur, nxt);
        const __half2* tmp = nxt;
        nxt = (__half2*)cur;
        cur = tmp;
    }

    k_final<<<NN/8, 256>>>(cur, b_tgt, out);       // launch 14
}